// round 9
// baseline (speedup 1.0000x reference)
#include <cuda_runtime.h>
#include <cuda_bf16.h>
#include <cstdint>

// V[b,n,f,t] = sum_p cos(obs[b,p,f,t] - tpd[b,p,n,f])
// 4-mic square degeneracy: pairs[3]==pairs[2], pairs[5]==-pairs[0] ->
// rank-8 contraction over 4 distinct phase groups (rep pairs 0,1,2,4).
//
// Round-9: one thread = (f_local, t-quad) covering ALL 36 n (no h-split ->
// each obs element sincos'd exactly ONCE; MUFU floor halves to ~3.4us).
// Block = (b, 2 freq bins), 160 threads. FFMA2 inner loop with coefficients
// stored PRE-DUPLICATED {c,c,s,s} in smem: 4 LDS.128 per n = 8 packed
// operands, zero packing MOVs. Store st.global.v2.u64 (16B).

#define NP    6
#define NG    4
#define NDIR  36
#define NF    257
#define NT    300
#define NB    4
#define FPB   2            // freq bins per block
#define NFB   129          // ceil(257/2)
#define NTQ   75           // t-quads

#define MUL2(d, a, b) asm("mul.rn.f32x2 %0, %1, %2;" : "=l"(d) : "l"(a), "l"(b))
#define FMA2(d, a, b) asm("fma.rn.f32x2 %0, %1, %2, %0;" : "+l"(d) : "l"(a), "l"(b))
#define STG_V2U64(p, x, y) \
    asm volatile("st.global.v2.u64 [%0], {%1, %2};" :: "l"(p), "l"(x), "l"(y) : "memory")

__device__ __forceinline__ unsigned long long pack2(float lo, float hi) {
    unsigned long long r;
    asm("mov.b64 %0, {%1, %2};" : "=l"(r) : "f"(lo), "f"(hi));
    return r;
}

__global__ __launch_bounds__(160)
void dirfeat_kernel(const float* __restrict__ obs,     // (B*P, F, T)
                    const float* __restrict__ azi,     // (B, N)
                    const float* __restrict__ ele,     // (B, N)
                    const float* __restrict__ pairs,   // (P, 3)
                    const float* __restrict__ freq,    // (F,)
                    float* __restrict__ out)           // (B, N, F, T)
{
    const int b  = blockIdx.x / NFB;
    const int f0 = (blockIdx.x - b * NFB) * FPB;
    const int tid = threadIdx.x;

    // csD[fl][n][4g + {0,1,2,3}] = {c, c, s, s} for group g (pre-duplicated)
    __shared__ __align__(16) float csD[FPB][NDIR][4 * NG];

    // ---- Phase 1: 288 steering entries (2f x 36n x 4g), 2 per thread ----
    for (int e = tid; e < FPB * NDIR * NG; e += 160) {
        const int fl = e / (NDIR * NG);
        const int r  = e - fl * (NDIR * NG);
        const int n  = r >> 2;
        const int g  = r & 3;
        const int rep = (g == 3) ? 4 : g;   // rep pair indices {0,1,2,4}
        const int f  = f0 + fl;
        if (f < NF) {
            const float a  = azi[b * NDIR + n];
            const float el = ele[b * NDIR + n];
            float sa, ca, se, ce;
            __sincosf(a,  &sa, &ca);
            __sincosf(el, &se, &ce);
            const float rx = se * ca, ry = se * sa, rz = ce;
            const float dot = pairs[rep * 3 + 0] * rx
                            + pairs[rep * 3 + 1] * ry
                            + pairs[rep * 3 + 2] * rz;
            const float tau = (6.283185307179586f / 343.0f) * dot * freq[f];
            float s, c;
            __sincosf(tau, &s, &c);
            csD[fl][n][4 * g + 0] = c;
            csD[fl][n][4 * g + 1] = c;
            csD[fl][n][4 * g + 2] = s;
            csD[fl][n][4 * g + 3] = s;
        }
    }
    __syncthreads();

    // ---- Phase 2: threads 0..149 -> (fl, t-quad); all 36 n per thread ----
    if (tid < FPB * NTQ) {
        const int fl = (tid >= NTQ) ? 1 : 0;
        const int tq = tid - fl * NTQ;
        const int f  = f0 + fl;
        if (f < NF) {
            const int t0 = tq * 4;

            const unsigned pstr = NF * NT;                 // 77100
            const float* ob = obs + (unsigned)((b * NP) * NF + f) * NT + t0;

            float uc[NG][4], us[NG][4];

            {   // group 0: pairs 0 and 5 (negated vector -> sin difference)
                const float4 oA = *reinterpret_cast<const float4*>(ob);
                const float4 oB = *reinterpret_cast<const float4*>(ob + 5 * pstr);
                float sA, cA, sB, cB;
                __sincosf(oA.x, &sA, &cA); __sincosf(oB.x, &sB, &cB);
                uc[0][0] = cA + cB; us[0][0] = sA - sB;
                __sincosf(oA.y, &sA, &cA); __sincosf(oB.y, &sB, &cB);
                uc[0][1] = cA + cB; us[0][1] = sA - sB;
                __sincosf(oA.z, &sA, &cA); __sincosf(oB.z, &sB, &cB);
                uc[0][2] = cA + cB; us[0][2] = sA - sB;
                __sincosf(oA.w, &sA, &cA); __sincosf(oB.w, &sB, &cB);
                uc[0][3] = cA + cB; us[0][3] = sA - sB;
            }
            {   // group 2: pairs 2 and 3 (identical vector -> sum)
                const float4 oA = *reinterpret_cast<const float4*>(ob + 2 * pstr);
                const float4 oB = *reinterpret_cast<const float4*>(ob + 3 * pstr);
                float sA, cA, sB, cB;
                __sincosf(oA.x, &sA, &cA); __sincosf(oB.x, &sB, &cB);
                uc[2][0] = cA + cB; us[2][0] = sA + sB;
                __sincosf(oA.y, &sA, &cA); __sincosf(oB.y, &sB, &cB);
                uc[2][1] = cA + cB; us[2][1] = sA + sB;
                __sincosf(oA.z, &sA, &cA); __sincosf(oB.z, &sB, &cB);
                uc[2][2] = cA + cB; us[2][2] = sA + sB;
                __sincosf(oA.w, &sA, &cA); __sincosf(oB.w, &sB, &cB);
                uc[2][3] = cA + cB; us[2][3] = sA + sB;
            }
            {   // group 1: pair 1 alone
                const float4 o = *reinterpret_cast<const float4*>(ob + 1 * pstr);
                __sincosf(o.x, &us[1][0], &uc[1][0]);
                __sincosf(o.y, &us[1][1], &uc[1][1]);
                __sincosf(o.z, &us[1][2], &uc[1][2]);
                __sincosf(o.w, &us[1][3], &uc[1][3]);
            }
            {   // group 3: pair 4 alone
                const float4 o = *reinterpret_cast<const float4*>(ob + 4 * pstr);
                __sincosf(o.x, &us[3][0], &uc[3][0]);
                __sincosf(o.y, &us[3][1], &uc[3][1]);
                __sincosf(o.z, &us[3][2], &uc[3][2]);
                __sincosf(o.w, &us[3][3], &uc[3][3]);
            }

            // Pack obs terms over t-pairs: U[plane][j]; j=0 -> {t0,t1}, j=1 -> {t2,t3}
            unsigned long long U[8][2];
#pragma unroll
            for (int g = 0; g < NG; g++) {
                U[2 * g][0]     = pack2(uc[g][0], uc[g][1]);
                U[2 * g][1]     = pack2(uc[g][2], uc[g][3]);
                U[2 * g + 1][0] = pack2(us[g][0], us[g][1]);
                U[2 * g + 1][1] = pack2(us[g][2], us[g][3]);
            }

            const unsigned nstride = NF * NT;
            float* outp = out + (unsigned)((b * NDIR) * NF + f) * NT + t0;

#pragma unroll
            for (int n = 0; n < NDIR; n++) {
                const ulonglong2* wp =
                    reinterpret_cast<const ulonglong2*>(&csD[fl][n][0]);
                const ulonglong2 w01 = wp[0];   // {c0,c0},{s0,s0}
                const ulonglong2 w23 = wp[1];   // {c1,c1},{s1,s1}
                const ulonglong2 w45 = wp[2];   // {c2,c2},{s2,s2}
                const ulonglong2 w67 = wp[3];   // {c3,c3},{s3,s3}

                unsigned long long acc01, acc23;
                MUL2(acc01, U[0][0], w01.x);     MUL2(acc23, U[0][1], w01.x);
                FMA2(acc01, U[1][0], w01.y);     FMA2(acc23, U[1][1], w01.y);
                FMA2(acc01, U[2][0], w23.x);     FMA2(acc23, U[2][1], w23.x);
                FMA2(acc01, U[3][0], w23.y);     FMA2(acc23, U[3][1], w23.y);
                FMA2(acc01, U[4][0], w45.x);     FMA2(acc23, U[4][1], w45.x);
                FMA2(acc01, U[5][0], w45.y);     FMA2(acc23, U[5][1], w45.y);
                FMA2(acc01, U[6][0], w67.x);     FMA2(acc23, U[6][1], w67.x);
                FMA2(acc01, U[7][0], w67.y);     FMA2(acc23, U[7][1], w67.y);

                STG_V2U64(outp + n * nstride, acc01, acc23);
            }
        }
    }
}

extern "C" void kernel_launch(void* const* d_in, const int* in_sizes, int n_in,
                              void* d_out, int out_size) {
    const float* obs   = (const float*)d_in[0];
    const float* azi   = (const float*)d_in[1];
    const float* ele   = (const float*)d_in[2];
    const float* pairs = (const float*)d_in[3];
    const float* freq  = (const float*)d_in[4];
    float* out = (float*)d_out;

    dim3 grid(NB * NFB);   // 516 blocks: (b, f-pair)
    dim3 block(160);       // 5 warps, 150 active in phase 2
    dirfeat_kernel<<<grid, block>>>(obs, azi, ele, pairs, freq, out);
}

// round 10
// speedup vs baseline: 1.0692x; 1.0692x over previous
#include <cuda_runtime.h>
#include <cuda_bf16.h>

// V[b,n,f,t] = sum_p cos(obs[b,p,f,t] - tpd[b,p,n,f])
// 4-mic square degeneracy: pairs[3]==pairs[2], pairs[5]==-pairs[0] ->
// rank-8 contraction over 4 distinct phase groups (rep pairs 0,1,2,4):
//   V = uc0*c0 + us0*s0 + uc1*c1 + us1*s1 + uc2*c2 + us2*s2 + uc3*c3 + us3*s3
//
// Round-10: occupancy by construction. Block = (b, 2 freq bins), 320 threads
// (300 active in phase 2). Thread = (f_local, t-PAIR), covers ALL 36 n:
// obs sincos once per element, only 16 combined obs registers -> natural
// regs ~44, no launch_bounds cap, no spills, ~4 blocks/SM resident.
// Inner loop per n: 2 LDS.128 (broadcast) + 16 FFMA + 1 STG.64.

#define NP    6
#define NG    4
#define NDIR  36
#define NF    257
#define NT    300
#define NB    4
#define FPB   2            // freq bins per block
#define NFB   129          // ceil(257/2)
#define NTP   150          // t-pairs per freq bin

__global__ __launch_bounds__(320)
void dirfeat_kernel(const float* __restrict__ obs,     // (B*P, F, T)
                    const float* __restrict__ azi,     // (B, N)
                    const float* __restrict__ ele,     // (B, N)
                    const float* __restrict__ pairs,   // (P, 3)
                    const float* __restrict__ freq,    // (F,)
                    float* __restrict__ out)           // (B, N, F, T)
{
    const int b  = blockIdx.x / NFB;
    const int f0 = (blockIdx.x - b * NFB) * FPB;
    const int tid = threadIdx.x;

    // cs[fl][n] = {c0,s0,c1,s1, c2,s2,c3,s3}
    __shared__ __align__(16) float cs[FPB][NDIR][2 * NG];

    // ---- Phase 1: 288 steering entries, one per thread ----
    if (tid < FPB * NDIR * NG) {
        const int fl = tid / (NDIR * NG);
        const int r  = tid - fl * (NDIR * NG);
        const int n  = r >> 2;
        const int g  = r & 3;
        const int rep = (g == 3) ? 4 : g;   // rep pair indices {0,1,2,4}
        const int f  = f0 + fl;
        if (f < NF) {
            const float a  = azi[b * NDIR + n];
            const float el = ele[b * NDIR + n];
            float sa, ca, se, ce;
            __sincosf(a,  &sa, &ca);
            __sincosf(el, &se, &ce);
            const float rx = se * ca, ry = se * sa, rz = ce;
            const float dot = pairs[rep * 3 + 0] * rx
                            + pairs[rep * 3 + 1] * ry
                            + pairs[rep * 3 + 2] * rz;
            const float tau = (6.283185307179586f / 343.0f) * dot * freq[f];
            float s, c;
            __sincosf(tau, &s, &c);
            cs[fl][n][2 * g]     = c;
            cs[fl][n][2 * g + 1] = s;
        }
    }
    __syncthreads();

    // ---- Phase 2: threads 0..299 -> (fl, t-pair); all 36 n per thread ----
    if (tid < FPB * NTP) {
        const int fl = (tid >= NTP) ? 1 : 0;
        const int tp = tid - fl * NTP;
        const int f  = f0 + fl;
        if (f < NF) {
            const int t0 = tp * 2;

            const unsigned pstr = NF * NT;                 // 77100
            const float* ob = obs + (unsigned)((b * NP) * NF + f) * NT + t0;

            // Combined obs terms (16 registers)
            float uc0x, uc0y, us0x, us0y;
            float uc1x, uc1y, us1x, us1y;
            float uc2x, uc2y, us2x, us2y;
            float uc3x, uc3y, us3x, us3y;

            {   // group 0: pairs 0 and 5 (negated vector -> sin difference)
                const float2 oA = *reinterpret_cast<const float2*>(ob);
                const float2 oB = *reinterpret_cast<const float2*>(ob + 5 * pstr);
                float sA, cA, sB, cB;
                __sincosf(oA.x, &sA, &cA); __sincosf(oB.x, &sB, &cB);
                uc0x = cA + cB; us0x = sA - sB;
                __sincosf(oA.y, &sA, &cA); __sincosf(oB.y, &sB, &cB);
                uc0y = cA + cB; us0y = sA - sB;
            }
            {   // group 2: pairs 2 and 3 (identical vector -> sum)
                const float2 oA = *reinterpret_cast<const float2*>(ob + 2 * pstr);
                const float2 oB = *reinterpret_cast<const float2*>(ob + 3 * pstr);
                float sA, cA, sB, cB;
                __sincosf(oA.x, &sA, &cA); __sincosf(oB.x, &sB, &cB);
                uc2x = cA + cB; us2x = sA + sB;
                __sincosf(oA.y, &sA, &cA); __sincosf(oB.y, &sB, &cB);
                uc2y = cA + cB; us2y = sA + sB;
            }
            {   // group 1: pair 1 alone
                const float2 o = *reinterpret_cast<const float2*>(ob + 1 * pstr);
                __sincosf(o.x, &us1x, &uc1x);
                __sincosf(o.y, &us1y, &uc1y);
            }
            {   // group 3: pair 4 alone
                const float2 o = *reinterpret_cast<const float2*>(ob + 4 * pstr);
                __sincosf(o.x, &us3x, &uc3x);
                __sincosf(o.y, &us3y, &uc3y);
            }

            const unsigned nstride = NF * NT;
            float* outA = out + (unsigned)((b * NDIR) * NF + f) * NT + t0;
            float* outB = outA + 18u * nstride;   // keep STG offsets in 24-bit range
            const float4* cpA = reinterpret_cast<const float4*>(&cs[fl][0][0]);
            const float4* cpB = reinterpret_cast<const float4*>(&cs[fl][18][0]);

#pragma unroll
            for (int i = 0; i < 18; i++) {
                {   // n = i
                    const float4 w0 = cpA[2 * i];       // c0 s0 c1 s1
                    const float4 w1 = cpA[2 * i + 1];   // c2 s2 c3 s3
                    float a0 = uc0x * w0.x;
                    float a1 = uc0y * w0.x;
                    a0 = fmaf(us0x, w0.y, a0);  a1 = fmaf(us0y, w0.y, a1);
                    a0 = fmaf(uc1x, w0.z, a0);  a1 = fmaf(uc1y, w0.z, a1);
                    a0 = fmaf(us1x, w0.w, a0);  a1 = fmaf(us1y, w0.w, a1);
                    a0 = fmaf(uc2x, w1.x, a0);  a1 = fmaf(uc2y, w1.x, a1);
                    a0 = fmaf(us2x, w1.y, a0);  a1 = fmaf(us2y, w1.y, a1);
                    a0 = fmaf(uc3x, w1.z, a0);  a1 = fmaf(uc3y, w1.z, a1);
                    a0 = fmaf(us3x, w1.w, a0);  a1 = fmaf(us3y, w1.w, a1);
                    *reinterpret_cast<float2*>(outA + i * nstride) =
                        make_float2(a0, a1);
                }
                {   // n = 18 + i
                    const float4 w0 = cpB[2 * i];
                    const float4 w1 = cpB[2 * i + 1];
                    float a0 = uc0x * w0.x;
                    float a1 = uc0y * w0.x;
                    a0 = fmaf(us0x, w0.y, a0);  a1 = fmaf(us0y, w0.y, a1);
                    a0 = fmaf(uc1x, w0.z, a0);  a1 = fmaf(uc1y, w0.z, a1);
                    a0 = fmaf(us1x, w0.w, a0);  a1 = fmaf(us1y, w0.w, a1);
                    a0 = fmaf(uc2x, w1.x, a0);  a1 = fmaf(uc2y, w1.x, a1);
                    a0 = fmaf(us2x, w1.y, a0);  a1 = fmaf(us2y, w1.y, a1);
                    a0 = fmaf(uc3x, w1.z, a0);  a1 = fmaf(uc3y, w1.z, a1);
                    a0 = fmaf(us3x, w1.w, a0);  a1 = fmaf(us3y, w1.w, a1);
                    *reinterpret_cast<float2*>(outB + i * nstride) =
                        make_float2(a0, a1);
                }
            }
        }
    }
}

extern "C" void kernel_launch(void* const* d_in, const int* in_sizes, int n_in,
                              void* d_out, int out_size) {
    const float* obs   = (const float*)d_in[0];
    const float* azi   = (const float*)d_in[1];
    const float* ele   = (const float*)d_in[2];
    const float* pairs = (const float*)d_in[3];
    const float* freq  = (const float*)d_in[4];
    float* out = (float*)d_out;

    dim3 grid(NB * NFB);   // 516 blocks: (b, f-pair)
    dim3 block(320);       // 10 warps, 300 active in phase 2
    dirfeat_kernel<<<grid, block>>>(obs, azi, ele, pairs, freq, out);
}